// round 5
// baseline (speedup 1.0000x reference)
#include <cuda_runtime.h>
#include <cstdint>

#define BATCH 16
#define CH 128          // channels == time steps == out channels
#define HH 112
#define WW 112

// ---------------- device globals (no allocation allowed) ----------------
__device__ float g_G[256];
__device__ float g_Bp[CH];
// A fragments, tf32 bits stored as float: [tap 9][kchunk 16][mtile 8][lane 32][4]
__device__ float g_AF[9 * 16 * 8 * 32 * 4];   // 576 KB

__device__ __forceinline__ uint32_t f2tf32(float v) {
    uint32_t r;
    asm("cvt.rna.tf32.f32 %0, %1;" : "=r"(r) : "f"(v));
    return r;
}
__device__ __forceinline__ uint32_t smem_u32(const void* p) {
    uint32_t a;
    asm("{ .reg .u64 t; cvta.to.shared.u64 t, %1; cvt.u32.u64 %0, t; }" : "=r"(a) : "l"(p));
    return a;
}

// ---------------------------------------------------------------------------
// G[m] = (l conv k)[m]; alpha == beta == exp(-1) exactly:
// G[m] = (1-beta) * e^-m * count(m)
// ---------------------------------------------------------------------------
__global__ void g_kernel() {
    int m = threadIdx.x;  // 256
    const float beta = 0.36787944117144233f;
    int lo = max(0, m - 127), hi = min(m, 127);
    int cnt = hi - lo + 1;
    g_G[m] = (cnt > 0) ? (1.0f - beta) * expf(-(float)m) * (float)cnt : 0.0f;
}

__global__ void bias_kernel(const float* __restrict__ b) {
    int t = threadIdx.x;  // 128
    float s = 0.0f;
    for (int o = 0; o < CH; o++) s += g_G[(t - o) & 255] * b[o];
    g_Bp[t] = s;
}

// ---------------------------------------------------------------------------
// Fused weights scattered into mma.m16n8k8 A-fragment layout (tf32).
// Wp[co][ci][tap] = sum_o G[(co-o)&255] * W[o][ci][tap]
// ---------------------------------------------------------------------------
__global__ void w2_kernel(const float* __restrict__ W) {
    __shared__ float Ws[128];
    __shared__ float Gs[256];
    int blk = blockIdx.x;               // ci*9 + tap : 1152 blocks
    int ci = blk / 9, tap = blk - ci * 9;
    int co = threadIdx.x;               // 128 threads
    Ws[co] = W[co * 1152 + ci * 9 + tap];
    Gs[co] = g_G[co];
    Gs[co + 128] = g_G[co + 128];
    __syncthreads();
    float s = 0.0f;
    #pragma unroll 8
    for (int o = 0; o < 128; o++) s += Gs[(co - o) & 255] * Ws[o];

    int r = co & 15, mt = co >> 4;
    int g = r & 7, rh = r >> 3;
    int kc = ci >> 3, c8 = ci & 7;
    int tg = c8 & 3, chf = c8 >> 2;
    int aidx = rh + 2 * chf;
    int lane = g * 4 + tg;
    g_AF[(((tap * 16 + kc) * 8 + mt) * 32 + lane) * 4 + aidx] =
        __uint_as_float(f2tf32(s));
}

// ---------------------------------------------------------------------------
// Main conv: implicit GEMM on mma.sync tf32, cp.async double-buffered staging.
// CTA = (b, h): M=128 co x N=112 px x K=1152. Warps: 4M x 2N, tile 32x56.
// ---------------------------------------------------------------------------
#define XS_W 120   // staged row width: pixel -1..118 (>=113 zero)
#define XS_ELEMS (16 * 3 * XS_W)

__global__ __launch_bounds__(256, 2) void conv_kernel(const float* __restrict__ x,
                                                      float* __restrict__ out) {
    __shared__ float xs[2][16][3][XS_W];   // 46080 B, double-buffered raw fp32

    const int tid = threadIdx.x, wid = tid >> 5, lane = tid & 31;
    const int g = lane >> 2, tg = lane & 3;
    const int wm = wid >> 1, wn = wid & 1;      // warp row 0..3, warp col 0..1
    const int b = blockIdx.y;
    const int h = blockIdx.x;

    // accumulators initialized with fused bias
    float acc[2][7][4];
    #pragma unroll
    for (int i = 0; i < 2; i++) {
        float blo = g_Bp[wm * 32 + i * 16 + g];
        float bhi = g_Bp[wm * 32 + i * 16 + g + 8];
        #pragma unroll
        for (int j = 0; j < 7; j++) {
            acc[i][j][0] = blo; acc[i][j][1] = blo;
            acc[i][j][2] = bhi; acc[i][j][3] = bhi;
        }
    }

    const float4* AF4 = (const float4*)g_AF;
    const uint32_t xs_base = smem_u32(&xs[0][0][0][0]);

    // ---- async stage of one 16-ci chunk into buffer buf (zero-fill padding)
    auto stage = [&](int cb, int buf) {
        const float* xb = x + ((size_t)b * CH + cb * 16) * HH * WW;
        uint32_t sdst = xs_base + (uint32_t)buf * (XS_ELEMS * 4);
        for (int i = tid; i < XS_ELEMS; i += 256) {
            int ci = i / (3 * XS_W);
            int rem = i - ci * (3 * XS_W);
            int kh = rem / XS_W;
            int w = rem - kh * XS_W;
            int gh = h - 1 + kh;
            int gw = w - 1;
            bool ok = ((unsigned)gh < (unsigned)HH) & ((unsigned)gw < (unsigned)WW);
            const float* src = ok ? (xb + (size_t)ci * HH * WW + gh * WW + gw) : xb;
            asm volatile("cp.async.ca.shared.global [%0], [%1], 4, %2;"
                         :: "r"(sdst + (uint32_t)i * 4), "l"(src), "r"(ok ? 4 : 0));
        }
        asm volatile("cp.async.commit_group;" ::: "memory");
    };

    stage(0, 0);   // prologue

    for (int cb = 0; cb < 8; cb++) {
        if (cb + 1 < 8) stage(cb + 1, (cb + 1) & 1);
        if (cb < 7) asm volatile("cp.async.wait_group 1;" ::: "memory");
        else        asm volatile("cp.async.wait_group 0;" ::: "memory");
        __syncthreads();

        const float* xbuf = &xs[cb & 1][0][0][0];
        #pragma unroll
        for (int ks = 0; ks < 2; ks++) {
            int kc = cb * 2 + ks;
            const float* xk = xbuf + (size_t)(ks * 8) * (3 * XS_W);
            #pragma unroll
            for (int kh = 0; kh < 3; kh++) {
                #pragma unroll
                for (int kw = 0; kw < 3; kw++) {
                    int tap = kh * 3 + kw;
                    float4 av0 = __ldg(&AF4[((tap * 16 + kc) * 8 + wm * 2 + 0) * 32 + lane]);
                    float4 av1 = __ldg(&AF4[((tap * 16 + kc) * 8 + wm * 2 + 1) * 32 + lane]);
                    uint32_t a0[4] = {__float_as_uint(av0.x), __float_as_uint(av0.y),
                                      __float_as_uint(av0.z), __float_as_uint(av0.w)};
                    uint32_t a1[4] = {__float_as_uint(av1.x), __float_as_uint(av1.y),
                                      __float_as_uint(av1.z), __float_as_uint(av1.w)};
                    #pragma unroll
                    for (int j = 0; j < 7; j++) {
                        int n = wn * 56 + j * 8 + g;     // output pixel col
                        int widx = n + kw;               // staged index (pixel n-1+kw)
                        uint32_t b0 = f2tf32(xk[(size_t)tg * (3 * XS_W) + kh * XS_W + widx]);
                        uint32_t b1 = f2tf32(xk[(size_t)(tg + 4) * (3 * XS_W) + kh * XS_W + widx]);
                        asm volatile(
                            "mma.sync.aligned.m16n8k8.row.col.f32.tf32.tf32.f32 "
                            "{%0,%1,%2,%3}, {%4,%5,%6,%7}, {%8,%9}, {%0,%1,%2,%3};"
                            : "+f"(acc[0][j][0]), "+f"(acc[0][j][1]),
                              "+f"(acc[0][j][2]), "+f"(acc[0][j][3])
                            : "r"(a0[0]), "r"(a0[1]), "r"(a0[2]), "r"(a0[3]),
                              "r"(b0), "r"(b1));
                        asm volatile(
                            "mma.sync.aligned.m16n8k8.row.col.f32.tf32.tf32.f32 "
                            "{%0,%1,%2,%3}, {%4,%5,%6,%7}, {%8,%9}, {%0,%1,%2,%3};"
                            : "+f"(acc[1][j][0]), "+f"(acc[1][j][1]),
                              "+f"(acc[1][j][2]), "+f"(acc[1][j][3])
                            : "r"(a1[0]), "r"(a1[1]), "r"(a1[2]), "r"(a1[3]),
                              "r"(b0), "r"(b1));
                    }
                }
            }
        }
        __syncthreads();
    }

    // ---- store: c0,c1 -> (row, 2tg..2tg+1), c2,c3 -> (row+8, ...)
    float* ob = out + ((size_t)b * CH * HH + h) * WW;
    #pragma unroll
    for (int i = 0; i < 2; i++) {
        int co = wm * 32 + i * 16 + g;
        #pragma unroll
        for (int j = 0; j < 7; j++) {
            int w = wn * 56 + j * 8 + tg * 2;
            *(float2*)&ob[(size_t)co * HH * WW + w] =
                make_float2(acc[i][j][0], acc[i][j][1]);
            *(float2*)&ob[(size_t)(co + 8) * HH * WW + w] =
                make_float2(acc[i][j][2], acc[i][j][3]);
        }
    }
}

// ---------------------------------------------------------------------------
extern "C" void kernel_launch(void* const* d_in, const int* in_sizes, int n_in,
                              void* d_out, int out_size) {
    const float* x = (const float*)d_in[0];   // (16,128,112,112)
    const float* W = (const float*)d_in[1];   // (128,128,3,3)
    const float* b = (const float*)d_in[2];   // (128,)
    float* out = (float*)d_out;

    g_kernel<<<1, 256>>>();
    bias_kernel<<<1, 128>>>(b);
    w2_kernel<<<1152, 128>>>(W);
    conv_kernel<<<dim3(HH, BATCH), 256>>>(x, out);
}

// round 6
// speedup vs baseline: 1.0940x; 1.0940x over previous
#include <cuda_runtime.h>
#include <cstdint>

#define BATCH 16
#define CH 128          // channels == time steps == out channels
#define HH 112
#define WW 112
#define HW (HH * WW)

// ---------------- device globals (no allocation allowed) ----------------
__device__ float g_G[256];
__device__ float g_Bp[CH];
// A fragments, tf32 bits stored as float: [tap 9][kchunk 16][mtile 8][lane 32][4]
__device__ float g_AF[9 * 16 * 8 * 32 * 4];   // 576 KB

__device__ __forceinline__ uint32_t f2tf32(float v) {
    uint32_t r;
    asm("cvt.rna.tf32.f32 %0, %1;" : "=r"(r) : "f"(v));
    return r;
}
__device__ __forceinline__ uint32_t smem_u32(const void* p) {
    uint32_t a;
    asm("{ .reg .u64 t; cvta.to.shared.u64 t, %1; cvt.u32.u64 %0, t; }" : "=r"(a) : "l"(p));
    return a;
}

// ---------------------------------------------------------------------------
// G[m] = (l conv k)[m]; alpha == beta == exp(-1) exactly:
// G[m] = (1-beta) * e^-m * count(m)
// ---------------------------------------------------------------------------
__global__ void g_kernel() {
    int m = threadIdx.x;  // 256
    const float beta = 0.36787944117144233f;
    int lo = max(0, m - 127), hi = min(m, 127);
    int cnt = hi - lo + 1;
    g_G[m] = (cnt > 0) ? (1.0f - beta) * expf(-(float)m) * (float)cnt : 0.0f;
}

__global__ void bias_kernel(const float* __restrict__ b) {
    int t = threadIdx.x;  // 128
    float s = 0.0f;
    for (int o = 0; o < CH; o++) s += g_G[(t - o) & 255] * b[o];
    g_Bp[t] = s;
}

// ---------------------------------------------------------------------------
// Fused weights scattered into mma.m16n8k8 A-fragment layout (tf32, .rna).
// Wp[co][ci][tap] = sum_o G[(co-o)&255] * W[o][ci][tap]
// ---------------------------------------------------------------------------
__global__ void w2_kernel(const float* __restrict__ W) {
    __shared__ float Ws[128];
    __shared__ float Gs[256];
    int blk = blockIdx.x;               // ci*9 + tap : 1152 blocks
    int ci = blk / 9, tap = blk - ci * 9;
    int co = threadIdx.x;               // 128 threads
    Ws[co] = W[co * 1152 + ci * 9 + tap];
    Gs[co] = g_G[co];
    Gs[co + 128] = g_G[co + 128];
    __syncthreads();
    float s = 0.0f;
    #pragma unroll 8
    for (int o = 0; o < 128; o++) s += Gs[(co - o) & 255] * Ws[o];

    int r = co & 15, mt = co >> 4;
    int g = r & 7, rh = r >> 3;
    int kc = ci >> 3, c8 = ci & 7;
    int tg = c8 & 3, chf = c8 >> 2;
    int aidx = rh + 2 * chf;
    int lane = g * 4 + tg;
    g_AF[(((tap * 16 + kc) * 8 + mt) * 32 + lane) * 4 + aidx] =
        __uint_as_float(f2tf32(s));
}

// ---------------------------------------------------------------------------
// Main conv: implicit GEMM on mma.sync tf32.
// CTA = (b, h): M=128 co x N=112 px x K=1152. Warps: 4M x 2N, tile 32x56.
// Smem x layout: [ks 2][kh 3][w 128][p 8], p interleaves ci pairs (tg, tg+4)
// -> B fragment for an MMA = one aligned LDS.64, min bank conflict.
// B operand fed as raw fp32 bits (HW tf32 truncation).
// ---------------------------------------------------------------------------
#define XS_FLOATS 6144          // 2*3*128*8 floats per buffer (24576 B)
#define SMEM_BYTES (2 * XS_FLOATS * 4 + XS_FLOATS * 4)   // 2 bufs + offset table

__global__ __launch_bounds__(256, 2) void conv_kernel(const float* __restrict__ x,
                                                      float* __restrict__ out) {
    extern __shared__ float dsm[];
    float* xs = dsm;                          // [2][XS_FLOATS]
    int* otab = (int*)(dsm + 2 * XS_FLOATS);  // gmem offset per smem slot (-1 = zero)

    const int tid = threadIdx.x, wid = tid >> 5, lane = tid & 31;
    const int g = lane >> 2, tg = lane & 3;
    const int wm = wid >> 1, wn = wid & 1;    // warp row 0..3, warp col 0..1
    const int b = blockIdx.y;
    const int h = blockIdx.x;

    // ---- offset table (chunk-invariant; each thread later reads its own rows)
    for (int i = tid; i < XS_FLOATS; i += 256) {
        int p = i & 7;
        int w = (i >> 3) & 127;
        int q = i >> 10;                      // 0..5 = ks*3 + kh
        int ks = (q >= 3) ? 1 : 0;
        int kh = q - 3 * ks;
        int ci = (ks << 3) | ((p & 1) << 2) | ((p >> 1) & 3);
        int gh = h - 1 + kh;
        int gw = w - 1;
        bool ok = ((unsigned)gh < (unsigned)HH) & ((unsigned)gw < (unsigned)WW);
        otab[i] = ok ? (ci * HW + gh * WW + gw) : -1;
    }

    // accumulators initialized with fused bias
    float acc[2][7][4];
    #pragma unroll
    for (int i = 0; i < 2; i++) {
        float blo = g_Bp[wm * 32 + i * 16 + g];
        float bhi = g_Bp[wm * 32 + i * 16 + g + 8];
        #pragma unroll
        for (int j = 0; j < 7; j++) {
            acc[i][j][0] = blo; acc[i][j][1] = blo;
            acc[i][j][2] = bhi; acc[i][j][3] = bhi;
        }
    }

    const float4* AF4 = (const float4*)g_AF;
    const uint32_t xs_b = smem_u32(xs);
    const float* xbase = x + (size_t)b * CH * HW;

    // ---- async stage one 16-ci chunk (raw fp32; zero-fill for padding)
    auto stage = [&](int cb, int buf) {
        const float* xb = xbase + (size_t)cb * 16 * HW;
        uint32_t d = xs_b + (uint32_t)buf * (XS_FLOATS * 4) + (uint32_t)tid * 4;
        #pragma unroll
        for (int it = 0; it < XS_FLOATS / 256; it++) {
            int i = tid + it * 256;
            int off = otab[i];
            const float* src = xb + (off >= 0 ? off : 0);
            int sz = (off >= 0) ? 4 : 0;
            asm volatile("cp.async.ca.shared.global [%0], [%1], 4, %2;"
                         :: "r"(d), "l"(src), "r"(sz));
            d += 1024;
        }
        asm volatile("cp.async.commit_group;" ::: "memory");
    };

    stage(0, 0);   // prologue

    for (int cb = 0; cb < 8; cb++) {
        if (cb + 1 < 8) stage(cb + 1, (cb + 1) & 1);
        if (cb < 7) asm volatile("cp.async.wait_group 1;" ::: "memory");
        else        asm volatile("cp.async.wait_group 0;" ::: "memory");
        __syncthreads();

        const float* xbuf = xs + (cb & 1) * XS_FLOATS;
        #pragma unroll
        for (int ks = 0; ks < 2; ks++) {
            int kc = cb * 2 + ks;
            // per-(ks) base: [ks][.][w = wn*56 + g][tg pair]
            const float* bp = xbuf + ks * 3072 + (wn * 56 + g) * 8 + tg * 2;
            #pragma unroll
            for (int kh = 0; kh < 3; kh++) {
                #pragma unroll
                for (int kw = 0; kw < 3; kw++) {
                    int tap = kh * 3 + kw;
                    float4 av0 = __ldg(&AF4[((tap * 16 + kc) * 8 + wm * 2 + 0) * 32 + lane]);
                    float4 av1 = __ldg(&AF4[((tap * 16 + kc) * 8 + wm * 2 + 1) * 32 + lane]);
                    uint32_t a0[4] = {__float_as_uint(av0.x), __float_as_uint(av0.y),
                                      __float_as_uint(av0.z), __float_as_uint(av0.w)};
                    uint32_t a1[4] = {__float_as_uint(av1.x), __float_as_uint(av1.y),
                                      __float_as_uint(av1.z), __float_as_uint(av1.w)};
                    #pragma unroll
                    for (int j = 0; j < 7; j++) {
                        // LDS.64 at [base + kh*4096B + (j*8+kw)*32B]
                        float2 bv = *(const float2*)(bp + kh * 1024 + (j * 8 + kw) * 8);
                        uint32_t b0 = __float_as_uint(bv.x);
                        uint32_t b1 = __float_as_uint(bv.y);
                        asm volatile(
                            "mma.sync.aligned.m16n8k8.row.col.f32.tf32.tf32.f32 "
                            "{%0,%1,%2,%3}, {%4,%5,%6,%7}, {%8,%9}, {%0,%1,%2,%3};"
                            : "+f"(acc[0][j][0]), "+f"(acc[0][j][1]),
                              "+f"(acc[0][j][2]), "+f"(acc[0][j][3])
                            : "r"(a0[0]), "r"(a0[1]), "r"(a0[2]), "r"(a0[3]),
                              "r"(b0), "r"(b1));
                        asm volatile(
                            "mma.sync.aligned.m16n8k8.row.col.f32.tf32.tf32.f32 "
                            "{%0,%1,%2,%3}, {%4,%5,%6,%7}, {%8,%9}, {%0,%1,%2,%3};"
                            : "+f"(acc[1][j][0]), "+f"(acc[1][j][1]),
                              "+f"(acc[1][j][2]), "+f"(acc[1][j][3])
                            : "r"(a1[0]), "r"(a1[1]), "r"(a1[2]), "r"(a1[3]),
                              "r"(b0), "r"(b1));
                    }
                }
            }
        }
        __syncthreads();
    }

    // ---- store: c0,c1 -> (row, 2tg..2tg+1), c2,c3 -> (row+8, ...)
    float* ob = out + ((size_t)b * CH * HH + h) * WW;
    #pragma unroll
    for (int i = 0; i < 2; i++) {
        int co = wm * 32 + i * 16 + g;
        #pragma unroll
        for (int j = 0; j < 7; j++) {
            int w = wn * 56 + j * 8 + tg * 2;
            *(float2*)&ob[(size_t)co * HW + w] =
                make_float2(acc[i][j][0], acc[i][j][1]);
            *(float2*)&ob[(size_t)(co + 8) * HW + w] =
                make_float2(acc[i][j][2], acc[i][j][3]);
        }
    }
}

// ---------------------------------------------------------------------------
extern "C" void kernel_launch(void* const* d_in, const int* in_sizes, int n_in,
                              void* d_out, int out_size) {
    const float* x = (const float*)d_in[0];   // (16,128,112,112)
    const float* W = (const float*)d_in[1];   // (128,128,3,3)
    const float* b = (const float*)d_in[2];   // (128,)
    float* out = (float*)d_out;

    cudaFuncSetAttribute(conv_kernel, cudaFuncAttributeMaxDynamicSharedMemorySize,
                         SMEM_BYTES);

    g_kernel<<<1, 256>>>();
    bias_kernel<<<1, 128>>>(b);
    w2_kernel<<<1152, 128>>>(W);
    conv_kernel<<<dim3(HH, BATCH), 256, SMEM_BYTES>>>(x, out);
}

// round 7
// speedup vs baseline: 1.7958x; 1.6415x over previous
#include <cuda_runtime.h>
#include <cuda_fp16.h>
#include <cstdint>

#define BATCH 16
#define CH 128          // channels == time steps == out channels
#define HH 112
#define WW 112
#define HW (HH * WW)

// ---------------- device globals (no allocation allowed) ----------------
__device__ float  g_G[256];
__device__ float  g_Bp[CH];
// A fragments (fused weights) in m16n8k16 A layout, fp16:
// [tap 9][cb 8][mtile 8][lane 32][8 halfs = a0..a3]
__device__ __half g_AFh[9 * 8 * 8 * 32 * 8];          // 294912 B
// Transposed fp16 x: [cb 8][b 16][h 112][w 112][ci16 permuted] as half2 pairs
__device__ __half2 g_Xt[(size_t)8 * BATCH * HH * WW * 8];   // 51.4 MB

__device__ __forceinline__ uint32_t smem_u32(const void* p) {
    uint32_t a;
    asm("{ .reg .u64 t; cvta.to.shared.u64 t, %1; cvt.u32.u64 %0, t; }" : "=r"(a) : "l"(p));
    return a;
}

// ---------------------------------------------------------------------------
// G[m] = (l conv k)[m]; alpha == beta == exp(-1) exactly:
// G[m] = (1-beta) * e^-m * count(m)
// ---------------------------------------------------------------------------
__global__ void g_kernel() {
    int m = threadIdx.x;  // 256
    const float beta = 0.36787944117144233f;
    int lo = max(0, m - 127), hi = min(m, 127);
    int cnt = hi - lo + 1;
    g_G[m] = (cnt > 0) ? (1.0f - beta) * expf(-(float)m) * (float)cnt : 0.0f;
}

__global__ void bias_kernel(const float* __restrict__ b) {
    int t = threadIdx.x;  // 128
    float s = 0.0f;
    for (int o = 0; o < CH; o++) s += g_G[(t - o) & 255] * b[o];
    g_Bp[t] = s;
}

// ---------------------------------------------------------------------------
// Fused weights scattered into mma.m16n8k16 A-fragment layout (fp16).
// Wp[co][ci][tap] = sum_o G[(co-o)&255] * W[o][ci][tap]
// A frag (per 16co x 16ci tile): a0=(g, 2tg..+1) a1=(g+8, 2tg..+1)
//                                a2=(g, 2tg+8..+9) a3=(g+8, 2tg+8..+9)
// ---------------------------------------------------------------------------
__global__ void w2_kernel(const float* __restrict__ W) {
    __shared__ float Ws[128];
    __shared__ float Gs[256];
    int blk = blockIdx.x;               // ci*9 + tap : 1152 blocks
    int ci = blk / 9, tap = blk - ci * 9;
    int co = threadIdx.x;               // 128 threads
    Ws[co] = W[co * 1152 + ci * 9 + tap];
    Gs[co] = g_G[co];
    Gs[co + 128] = g_G[co + 128];
    __syncthreads();
    float s = 0.0f;
    #pragma unroll 8
    for (int o = 0; o < 128; o++) s += Gs[(co - o) & 255] * Ws[o];

    int r = co & 15, mt = co >> 4;
    int g = r & 7, rh = r >> 3;                 // rh -> a1/a3 (row+8)
    int kc = ci >> 4, c16 = ci & 15;
    int tg = (c16 >> 1) & 3, bslot = c16 & 1, c = c16 >> 3;   // c -> k+8 (a2/a3)
    int reg = rh + 2 * c;
    int lane = g * 4 + tg;
    g_AFh[((((size_t)tap * 8 + kc) * 8 + mt) * 32 + lane) * 8 + reg * 2 + bslot] =
        __float2half_rn(s);
}

// ---------------------------------------------------------------------------
// Transpose x -> fp16, layout [cb][b][h][w][ci16 perm], perm matches B frags:
// p = tg*4 + c*2 + bslot  <->  ci = 2*tg + bslot + 8*c
// half2 slot p2 = tg*2 + c holds (ci, ci+1) with ci = 2*tg + 8*c
// ---------------------------------------------------------------------------
__global__ void xt_kernel(const float* __restrict__ x) {
    __shared__ float t[16][113];
    int h = blockIdx.x, cb = blockIdx.y, b = blockIdx.z;
    int tid = threadIdx.x;   // 128
    const float* xp = x + ((size_t)b * CH + cb * 16) * HW + h * WW;
    for (int i = tid; i < 16 * 112; i += 128) {
        int q = i / 112, w = i - q * 112;
        t[q][w] = xp[(size_t)q * HW + w];
    }
    __syncthreads();
    __half2* dst = g_Xt + ((((size_t)cb * BATCH + b) * HH + h) * WW) * 8;
    for (int i = tid; i < 112 * 8; i += 128) {
        int p2 = i & 7, w = i >> 3;
        int tg = p2 >> 1, c = p2 & 1;
        int ca = 2 * tg + 8 * c;
        dst[(size_t)w * 8 + p2] = __floats2half2_rn(t[ca][w], t[ca + 1][w]);
    }
}

// ---------------------------------------------------------------------------
// Main conv: implicit GEMM on mma.sync.m16n8k16 fp16 (f32 accum).
// CTA = (b, h): M=128 co x N=112 px x K=1152. Warps: 4M x 2N, tile 32co x 56px.
// Smem x: [row 3][w 120][ci16 perm] halfs, double-buffered; staged via
// contiguous 16B cp.async from g_Xt. B frag = one LDS.64.
// ---------------------------------------------------------------------------
#define XBUF_BYTES 11520        // 3 * 120 * 32
#define NSLOT 720               // 3 * 120 * 2 (16B slots)

__global__ __launch_bounds__(256, 2) void conv_kernel(float* __restrict__ out) {
    __shared__ __align__(16) char xsm[2][XBUF_BYTES];
    __shared__ int otab[NSLOT];

    const int tid = threadIdx.x, wid = tid >> 5, lane = tid & 31;
    const int g = lane >> 2, tg = lane & 3;
    const int wm = wid >> 1, wn = wid & 1;    // warp row 0..3, warp col 0..1
    const int b = blockIdx.y;
    const int h = blockIdx.x;

    // ---- offset table: per 16B slot, byte offset into x_t (cb,b)-plane, or -1
    for (int i = tid; i < NSLOT; i += 256) {
        int blk = i & 1;
        int w = (i >> 1) % 120;
        int row = (i >> 1) / 120;
        int gh = h - 1 + row;
        int gw = w - 1;
        bool ok = ((unsigned)gh < (unsigned)HH) & ((unsigned)gw < (unsigned)WW);
        otab[i] = ok ? ((gh * WW + gw) * 32 + blk * 16) : -1;
    }

    // accumulators initialized with fused bias
    float acc[2][7][4];
    #pragma unroll
    for (int i = 0; i < 2; i++) {
        float blo = g_Bp[wm * 32 + i * 16 + g];
        float bhi = g_Bp[wm * 32 + i * 16 + g + 8];
        #pragma unroll
        for (int j = 0; j < 7; j++) {
            acc[i][j][0] = blo; acc[i][j][1] = blo;
            acc[i][j][2] = bhi; acc[i][j][3] = bhi;
        }
    }

    const uint4* AF4 = (const uint4*)g_AFh;
    const uint32_t xs_b = smem_u32(&xsm[0][0]);
    const char* xtb = (const char*)g_Xt;

    // ---- async stage one 16-ci chunk (fp16, 16B contiguous copies)
    auto stage = [&](int cb, int buf) {
        const char* src_base = xtb + (((size_t)cb * BATCH + b) * HH) * WW * 32;
        uint32_t d = xs_b + (uint32_t)buf * XBUF_BYTES + (uint32_t)tid * 16;
        #pragma unroll
        for (int it = 0; it < 3; it++) {
            int i = tid + it * 256;
            if (i < NSLOT) {
                int off = otab[i];
                const char* src = src_base + (off >= 0 ? off : 0);
                int sz = (off >= 0) ? 16 : 0;
                asm volatile("cp.async.ca.shared.global [%0], [%1], 16, %2;"
                             :: "r"(d), "l"(src), "r"(sz));
            }
            d += 4096;
        }
        asm volatile("cp.async.commit_group;" ::: "memory");
    };

    stage(0, 0);   // prologue

    for (int cb = 0; cb < 8; cb++) {
        if (cb + 1 < 8) stage(cb + 1, (cb + 1) & 1);
        if (cb < 7) asm volatile("cp.async.wait_group 1;" ::: "memory");
        else        asm volatile("cp.async.wait_group 0;" ::: "memory");
        __syncthreads();

        // per-warp/lane B base: [row][w = wn*56 + g + (j*8+kw)][p = tg*4]
        const char* bp = &xsm[cb & 1][0] + (wn * 56 + g) * 32 + tg * 8;

        #pragma unroll
        for (int kh = 0; kh < 3; kh++) {
            #pragma unroll
            for (int kw = 0; kw < 3; kw++) {
                int tap = kh * 3 + kw;
                uint4 av0 = __ldg(&AF4[(((size_t)tap * 8 + cb) * 8 + wm * 2 + 0) * 32 + lane]);
                uint4 av1 = __ldg(&AF4[(((size_t)tap * 8 + cb) * 8 + wm * 2 + 1) * 32 + lane]);
                #pragma unroll
                for (int j = 0; j < 7; j++) {
                    // one LDS.64: {b0 = ci 2tg..2tg+1, b1 = ci 2tg+8..2tg+9}
                    uint2 bv = *(const uint2*)(bp + kh * 3840 + (j * 8 + kw) * 32);
                    asm volatile(
                        "mma.sync.aligned.m16n8k16.row.col.f32.f16.f16.f32 "
                        "{%0,%1,%2,%3}, {%4,%5,%6,%7}, {%8,%9}, {%0,%1,%2,%3};"
                        : "+f"(acc[0][j][0]), "+f"(acc[0][j][1]),
                          "+f"(acc[0][j][2]), "+f"(acc[0][j][3])
                        : "r"(av0.x), "r"(av0.y), "r"(av0.z), "r"(av0.w),
                          "r"(bv.x), "r"(bv.y));
                    asm volatile(
                        "mma.sync.aligned.m16n8k16.row.col.f32.f16.f16.f32 "
                        "{%0,%1,%2,%3}, {%4,%5,%6,%7}, {%8,%9}, {%0,%1,%2,%3};"
                        : "+f"(acc[1][j][0]), "+f"(acc[1][j][1]),
                          "+f"(acc[1][j][2]), "+f"(acc[1][j][3])
                        : "r"(av1.x), "r"(av1.y), "r"(av1.z), "r"(av1.w),
                          "r"(bv.x), "r"(bv.y));
                }
            }
        }
        __syncthreads();
    }

    // ---- store: c0,c1 -> (row g, px 2tg..2tg+1), c2,c3 -> (row g+8, ...)
    float* ob = out + ((size_t)b * CH * HH + h) * WW;
    #pragma unroll
    for (int i = 0; i < 2; i++) {
        int co = wm * 32 + i * 16 + g;
        #pragma unroll
        for (int j = 0; j < 7; j++) {
            int w = wn * 56 + j * 8 + tg * 2;
            *(float2*)&ob[(size_t)co * HW + w] =
                make_float2(acc[i][j][0], acc[i][j][1]);
            *(float2*)&ob[(size_t)(co + 8) * HW + w] =
                make_float2(acc[i][j][2], acc[i][j][3]);
        }
    }
}

// ---------------------------------------------------------------------------
extern "C" void kernel_launch(void* const* d_in, const int* in_sizes, int n_in,
                              void* d_out, int out_size) {
    const float* x = (const float*)d_in[0];   // (16,128,112,112)
    const float* W = (const float*)d_in[1];   // (128,128,3,3)
    const float* b = (const float*)d_in[2];   // (128,)
    float* out = (float*)d_out;

    g_kernel<<<1, 256>>>();
    bias_kernel<<<1, 128>>>(b);
    w2_kernel<<<1152, 128>>>(W);
    xt_kernel<<<dim3(HH, 8, BATCH), 128>>>(x);
    conv_kernel<<<dim3(HH, BATCH), 256>>>(out);
}

// round 8
// speedup vs baseline: 1.9701x; 1.0970x over previous
#include <cuda_runtime.h>
#include <cuda_fp16.h>
#include <cstdint>

#define BATCH 16
#define CH 128          // channels == time steps == out channels
#define HH 112
#define WW 112
#define HW (HH * WW)

// ---------------- device globals (no allocation allowed) ----------------
__device__ float  g_G[256];
__device__ float  g_Bp[CH];
// A fragments (fused weights) in m16n8k16 A layout, fp16:
// [tap 9][cb 8][mtile 8][lane 32][8 halfs = a0..a3]
__device__ __half g_AFh[9 * 8 * 8 * 32 * 8];          // 294912 B
// Transposed fp16 x: [cb 8][b 16][h 112][w 112][ci16 permuted] as half2 pairs
__device__ __half2 g_Xt[(size_t)8 * BATCH * HH * WW * 8];   // 51.4 MB

__device__ __forceinline__ uint32_t smem_u32(const void* p) {
    uint32_t a;
    asm("{ .reg .u64 t; cvta.to.shared.u64 t, %1; cvt.u32.u64 %0, t; }" : "=r"(a) : "l"(p));
    return a;
}

// ---------------------------------------------------------------------------
// G[m] = (l conv k)[m]; alpha == beta == exp(-1) exactly:
// G[m] = (1-beta) * e^-m * count(m)
// ---------------------------------------------------------------------------
__global__ void g_kernel() {
    int m = threadIdx.x;  // 256
    const float beta = 0.36787944117144233f;
    int lo = max(0, m - 127), hi = min(m, 127);
    int cnt = hi - lo + 1;
    g_G[m] = (cnt > 0) ? (1.0f - beta) * expf(-(float)m) * (float)cnt : 0.0f;
}

__global__ void bias_kernel(const float* __restrict__ b) {
    int t = threadIdx.x;  // 128
    float s = 0.0f;
    for (int o = 0; o < CH; o++) s += g_G[(t - o) & 255] * b[o];
    g_Bp[t] = s;
}

// ---------------------------------------------------------------------------
// Fused weights scattered into mma.m16n8k16 A-fragment layout (fp16).
// Wp[co][ci][tap] = sum_o G[(co-o)&255] * W[o][ci][tap]
// ---------------------------------------------------------------------------
__global__ void w2_kernel(const float* __restrict__ W) {
    __shared__ float Ws[128];
    __shared__ float Gs[256];
    int blk = blockIdx.x;               // ci*9 + tap : 1152 blocks
    int ci = blk / 9, tap = blk - ci * 9;
    int co = threadIdx.x;               // 128 threads
    Ws[co] = W[co * 1152 + ci * 9 + tap];
    Gs[co] = g_G[co];
    Gs[co + 128] = g_G[co + 128];
    __syncthreads();
    float s = 0.0f;
    #pragma unroll 8
    for (int o = 0; o < 128; o++) s += Gs[(co - o) & 255] * Ws[o];

    int r = co & 15, mt = co >> 4;
    int g = r & 7, rh = r >> 3;                 // rh -> a1/a3 (row+8)
    int kc = ci >> 4, c16 = ci & 15;
    int tg = (c16 >> 1) & 3, bslot = c16 & 1, c = c16 >> 3;   // c -> k+8 (a2/a3)
    int reg = rh + 2 * c;
    int lane = g * 4 + tg;
    g_AFh[((((size_t)tap * 8 + kc) * 8 + mt) * 32 + lane) * 8 + reg * 2 + bslot] =
        __float2half_rn(s);
}

// ---------------------------------------------------------------------------
// Transpose x -> fp16 [cb][b][h][w][ci16 perm] (32B per w).
// half2 slot p2 = tg*2 + c holds (ci, ci+1), ci = 2*tg + 8*c.
// Vectorized: float4 staging, per-thread w packing, STG.128 output.
// ---------------------------------------------------------------------------
__global__ void xt_kernel(const float* __restrict__ x) {
    __shared__ float t[16][116];   // stride 116 floats (16B-aligned rows)
    int h = blockIdx.x, cb = blockIdx.y, b = blockIdx.z;
    int tid = threadIdx.x;   // 128
    const float* xp = x + ((size_t)b * CH + cb * 16) * HW + h * WW;
    // stage 16 rows x 112 floats as float4
    for (int i = tid; i < 16 * 28; i += 128) {
        int q = i >> 5, c4 = i & 31;         // 28 float4 per row; pad loop shape
        q = i / 28; c4 = i - q * 28;
        ((float4*)t[q])[c4] = *(const float4*)(xp + (size_t)q * HW + c4 * 4);
    }
    __syncthreads();
    __half2* dst = g_Xt + ((((size_t)cb * BATCH + b) * HH + h) * WW) * 8;
    if (tid < 112) {
        int w = tid;
        uint32_t h2[8];
        #pragma unroll
        for (int p2 = 0; p2 < 8; p2++) {
            int tg = p2 >> 1, c = p2 & 1;
            int ca = 2 * tg + 8 * c;
            __half2 v = __floats2half2_rn(t[ca][w], t[ca + 1][w]);
            h2[p2] = *(uint32_t*)&v;
        }
        uint4* d = (uint4*)(dst + (size_t)w * 8);
        d[0] = make_uint4(h2[0], h2[1], h2[2], h2[3]);
        d[1] = make_uint4(h2[4], h2[5], h2[6], h2[7]);
    }
}

// ---------------------------------------------------------------------------
// Main conv: implicit GEMM on mma.sync.m16n8k16 fp16 (f32 accum).
// CTA = (b, h), 128 threads, 4 warps in 2M x 2N; warp tile 64co x 56px
// (4 m-frags x 7 n-frags, 112 accums). B frag = one LDS.64 feeding 4 MMAs.
// ---------------------------------------------------------------------------
#define XBUF_BYTES 11520        // 3 * 120 * 32
#define NSLOT 720               // 3 * 120 * 2 (16B slots)

__global__ __launch_bounds__(128, 2) void conv_kernel(float* __restrict__ out) {
    __shared__ __align__(16) char xsm[2][XBUF_BYTES];
    __shared__ int otab[NSLOT];

    const int tid = threadIdx.x, wid = tid >> 5, lane = tid & 31;
    const int g = lane >> 2, tg = lane & 3;
    const int wm = wid >> 1, wn = wid & 1;    // 2x2 warp grid
    const int b = blockIdx.y;
    const int h = blockIdx.x;

    // ---- offset table: per 16B slot, byte offset into x_t (cb,b)-plane, or -1
    for (int i = tid; i < NSLOT; i += 128) {
        int blk = i & 1;
        int w = (i >> 1) % 120;
        int row = (i >> 1) / 120;
        int gh = h - 1 + row;
        int gw = w - 1;
        bool ok = ((unsigned)gh < (unsigned)HH) & ((unsigned)gw < (unsigned)WW);
        otab[i] = ok ? ((gh * WW + gw) * 32 + blk * 16) : -1;
    }

    // accumulators initialized with fused bias
    float acc[4][7][4];
    #pragma unroll
    for (int i = 0; i < 4; i++) {
        float blo = g_Bp[wm * 64 + i * 16 + g];
        float bhi = g_Bp[wm * 64 + i * 16 + g + 8];
        #pragma unroll
        for (int j = 0; j < 7; j++) {
            acc[i][j][0] = blo; acc[i][j][1] = blo;
            acc[i][j][2] = bhi; acc[i][j][3] = bhi;
        }
    }

    const uint4* AF4 = (const uint4*)g_AFh;
    const uint32_t xs_b = smem_u32(&xsm[0][0]);
    const char* xtb = (const char*)g_Xt;

    // ---- async stage one 16-ci chunk (fp16, 16B contiguous copies)
    auto stage = [&](int cb, int buf) {
        const char* src_base = xtb + (((size_t)cb * BATCH + b) * HH) * WW * 32;
        uint32_t d = xs_b + (uint32_t)buf * XBUF_BYTES + (uint32_t)tid * 16;
        #pragma unroll
        for (int it = 0; it < 6; it++) {
            int i = tid + it * 128;
            if (i < NSLOT) {
                int off = otab[i];
                const char* src = src_base + (off >= 0 ? off : 0);
                int sz = (off >= 0) ? 16 : 0;
                asm volatile("cp.async.ca.shared.global [%0], [%1], 16, %2;"
                             :: "r"(d), "l"(src), "r"(sz));
            }
            d += 2048;
        }
        asm volatile("cp.async.commit_group;" ::: "memory");
    };

    stage(0, 0);   // prologue

    for (int cb = 0; cb < 8; cb++) {
        if (cb + 1 < 8) stage(cb + 1, (cb + 1) & 1);
        if (cb < 7) asm volatile("cp.async.wait_group 1;" ::: "memory");
        else        asm volatile("cp.async.wait_group 0;" ::: "memory");
        __syncthreads();

        // per-warp/lane B base: [row][w = wn*56 + g + (j*8+kw)][p = tg*4]
        const char* bp = &xsm[cb & 1][0] + (wn * 56 + g) * 32 + tg * 8;

        #pragma unroll
        for (int kh = 0; kh < 3; kh++) {
            #pragma unroll
            for (int kw = 0; kw < 3; kw++) {
                int tap = kh * 3 + kw;
                uint4 av[4];
                #pragma unroll
                for (int i = 0; i < 4; i++)
                    av[i] = __ldg(&AF4[(((size_t)tap * 8 + cb) * 8 + wm * 4 + i) * 32 + lane]);
                #pragma unroll
                for (int j = 0; j < 7; j++) {
                    // one LDS.64: {b0 = ci 2tg..2tg+1, b1 = ci 2tg+8..2tg+9}
                    uint2 bv = *(const uint2*)(bp + kh * 3840 + (j * 8 + kw) * 32);
                    #pragma unroll
                    for (int i = 0; i < 4; i++) {
                        asm volatile(
                            "mma.sync.aligned.m16n8k16.row.col.f32.f16.f16.f32 "
                            "{%0,%1,%2,%3}, {%4,%5,%6,%7}, {%8,%9}, {%0,%1,%2,%3};"
                            : "+f"(acc[i][j][0]), "+f"(acc[i][j][1]),
                              "+f"(acc[i][j][2]), "+f"(acc[i][j][3])
                            : "r"(av[i].x), "r"(av[i].y), "r"(av[i].z), "r"(av[i].w),
                              "r"(bv.x), "r"(bv.y));
                    }
                }
            }
        }
        __syncthreads();
    }

    // ---- store: c0,c1 -> (row g, px 2tg..2tg+1), c2,c3 -> (row g+8, ...)
    float* ob = out + ((size_t)b * CH * HH + h) * WW;
    #pragma unroll
    for (int i = 0; i < 4; i++) {
        int co = wm * 64 + i * 16 + g;
        #pragma unroll
        for (int j = 0; j < 7; j++) {
            int w = wn * 56 + j * 8 + tg * 2;
            *(float2*)&ob[(size_t)co * HW + w] =
                make_float2(acc[i][j][0], acc[i][j][1]);
            *(float2*)&ob[(size_t)(co + 8) * HW + w] =
                make_float2(acc[i][j][2], acc[i][j][3]);
        }
    }
}

// ---------------------------------------------------------------------------
extern "C" void kernel_launch(void* const* d_in, const int* in_sizes, int n_in,
                              void* d_out, int out_size) {
    const float* x = (const float*)d_in[0];   // (16,128,112,112)
    const float* W = (const float*)d_in[1];   // (128,128,3,3)
    const float* b = (const float*)d_in[2];   // (128,)
    float* out = (float*)d_out;

    g_kernel<<<1, 256>>>();
    bias_kernel<<<1, 128>>>(b);
    w2_kernel<<<1152, 128>>>(W);
    xt_kernel<<<dim3(HH, 8, BATCH), 128>>>(x);
    conv_kernel<<<dim3(HH, BATCH), 128>>>(out);
}